// round 1
// baseline (speedup 1.0000x reference)
#include <cuda_runtime.h>

#define NCLS 19
#define CH   256
#define HW   16384      // 128*128
#define BSZ  8
#define NPIX (BSZ*HW)   // 131072
#define NQ   2975
#define INV_T 5.0f      // 1/0.2
#define CPT  8          // channels per thread in sums kernel

// ---- device scratch (static allocation is allowed) ----
__device__ float          g_sums[NCLS*CH];
__device__ int            g_counts[NCLS];
__device__ float          g_keys[NCLS*CH];
__device__ unsigned char  g_pred[NPIX];
__device__ float          g_qsum[CH*NQ];   // ~3 MB, L2-resident

// ---------------------------------------------------------------------------
// init: zero sums/counts and the loss slot
// ---------------------------------------------------------------------------
__global__ void init_kernel(float* out_loss) {
    int t = blockIdx.x * blockDim.x + threadIdx.x;
    if (t < NCLS * CH) g_sums[t] = 0.0f;
    if (t < NCLS)      g_counts[t] = 0;
    if (t == 0)        *out_loss = 0.0f;
}

// ---------------------------------------------------------------------------
// pred: argmax over classes + copy res -> out + class histogram
// one thread per pixel (b,p); 19 coalesced strided loads + stores
// ---------------------------------------------------------------------------
__global__ void pred_kernel(const float* __restrict__ res, float* __restrict__ out) {
    __shared__ int hist[NCLS];
    int tid = threadIdx.x;
    if (tid < NCLS) hist[tid] = 0;
    __syncthreads();

    int t = blockIdx.x * 256 + tid;          // 0..NPIX-1
    int b = t >> 14;
    int p = t & (HW - 1);
    const float* r = res + b * NCLS * HW + p;
    float*       o = out + b * NCLS * HW + p;

    float best = r[0];
    o[0] = best;
    int bk = 0;
    #pragma unroll
    for (int k = 1; k < NCLS; k++) {
        float v = r[k * HW];
        o[k * HW] = v;
        if (v > best) { best = v; bk = k; }   // first-max wins (argmax semantics)
    }
    g_pred[t] = (unsigned char)bk;
    atomicAdd(&hist[bk], 1);
    __syncthreads();
    if (tid < NCLS) atomicAdd(&g_counts[tid], hist[tid]);
}

// ---------------------------------------------------------------------------
// sums: per-class masked sum of fea. grid (32 cgroups, 8 batch), 256 threads.
// Each thread keeps acc[19][8] in registers; mask computed once per class,
// then CPT FFMAs. Warp shfl-reduce, lane0 atomics to global (311K atomics).
// ---------------------------------------------------------------------------
__global__ void __launch_bounds__(256, 1) sums_kernel(const float* __restrict__ fea) {
    int b  = blockIdx.y;
    int c0 = blockIdx.x * CPT;

    float acc[NCLS][CPT];
    #pragma unroll
    for (int k = 0; k < NCLS; k++)
        #pragma unroll
        for (int i = 0; i < CPT; i++) acc[k][i] = 0.0f;

    const float* fbase = fea + (b * CH + c0) * HW;
    const unsigned char* pr = g_pred + b * HW;

    for (int p = threadIdx.x; p < HW; p += 256) {
        int pk = pr[p];
        float v[CPT];
        #pragma unroll
        for (int i = 0; i < CPT; i++) v[i] = fbase[i * HW + p];
        #pragma unroll
        for (int k = 0; k < NCLS; k++) {
            float m = (pk == k) ? 1.0f : 0.0f;   // ISETP+SEL once, reused for CPT FFMAs
            #pragma unroll
            for (int i = 0; i < CPT; i++)
                acc[k][i] = fmaf(m, v[i], acc[k][i]);
        }
    }

    // warp reduce each accumulator, lane0 adds to global
    #pragma unroll
    for (int k = 0; k < NCLS; k++) {
        #pragma unroll
        for (int i = 0; i < CPT; i++) {
            float s = acc[k][i];
            s += __shfl_down_sync(0xffffffffu, s, 16);
            s += __shfl_down_sync(0xffffffffu, s, 8);
            s += __shfl_down_sync(0xffffffffu, s, 4);
            s += __shfl_down_sync(0xffffffffu, s, 2);
            s += __shfl_down_sync(0xffffffffu, s, 1);
            if ((threadIdx.x & 31) == 0)
                atomicAdd(&g_sums[k * CH + c0 + i], s);
        }
    }
}

// ---------------------------------------------------------------------------
// keys: masked mean + L2 normalize along C. One block per class.
// ---------------------------------------------------------------------------
__global__ void keys_kernel() {
    int k = blockIdx.x;
    int c = threadIdx.x;                    // 256 threads
    float cnt = (float)max(g_counts[k], 1);
    float v = g_sums[k * CH + c] / cnt;

    __shared__ float red[8];
    __shared__ float snorm;
    float ss = v * v;
    #pragma unroll
    for (int o = 16; o; o >>= 1) ss += __shfl_xor_sync(0xffffffffu, ss, o);
    if ((c & 31) == 0) red[c >> 5] = ss;
    __syncthreads();
    if (c == 0) {
        float t = 0.0f;
        #pragma unroll
        for (int i = 0; i < 8; i++) t += red[i];
        snorm = fmaxf(sqrtf(t), 1e-12f);
    }
    __syncthreads();
    g_keys[k * CH + c] = v / snorm;
}

// ---------------------------------------------------------------------------
// qsum[c][j] = sum_k queues[k][c][j]
// ---------------------------------------------------------------------------
__global__ void qsum_kernel(const float* __restrict__ queues) {
    int t = blockIdx.x * 256 + threadIdx.x;
    if (t >= CH * NQ) return;
    float s = 0.0f;
    #pragma unroll
    for (int k = 0; k < NCLS; k++) s += queues[k * CH * NQ + t];
    g_qsum[t] = s;
}

// ---------------------------------------------------------------------------
// lse: one block per (k,c) row. Row cached in registers; stable 2-pass LSE.
// ---------------------------------------------------------------------------
__global__ void __launch_bounds__(256) lse_kernel(const float* __restrict__ queues,
                                                  float* __restrict__ out_loss) {
    int kc = blockIdx.x;              // 0..NCLS*CH-1
    int k  = kc >> 8;
    int c  = kc & 255;
    float a = g_keys[kc] * INV_T;
    const float* qrow  = queues + (long)kc * NQ;
    const float* qsrow = g_qsum + (long)c * NQ;

    int tid = threadIdx.x;
    float q[12], qs[12];
    float mx = -3.4e38f;
    #pragma unroll
    for (int i = 0; i < 12; i++) {
        int j = tid + i * 256;
        if (j < NQ) {
            q[i]  = qrow[j];
            qs[i] = qsrow[j];
            float x1 = a * q[i];
            float x2 = a * (qs[i] - q[i]);
            mx = fmaxf(mx, fmaxf(x1, x2));
        }
    }

    __shared__ float red[8];
    __shared__ float smax;
    #pragma unroll
    for (int o = 16; o; o >>= 1) mx = fmaxf(mx, __shfl_xor_sync(0xffffffffu, mx, o));
    if ((tid & 31) == 0) red[tid >> 5] = mx;
    __syncthreads();
    if (tid == 0) {
        float m = red[0];
        #pragma unroll
        for (int i = 1; i < 8; i++) m = fmaxf(m, red[i]);
        smax = m;
    }
    __syncthreads();
    float m = smax;
    __syncthreads();                 // protect red[] before reuse

    float s = 0.0f;
    #pragma unroll
    for (int i = 0; i < 12; i++) {
        int j = tid + i * 256;
        if (j < NQ) {
            float x1 = a * q[i];
            float x2 = a * (qs[i] - q[i]);
            s += __expf(x1 - m) + __expf(x2 - m);
        }
    }
    #pragma unroll
    for (int o = 16; o; o >>= 1) s += __shfl_xor_sync(0xffffffffu, s, o);
    if ((tid & 31) == 0) red[tid >> 5] = s;
    __syncthreads();
    if (tid == 0) {
        float tot = 0.0f;
        #pragma unroll
        for (int i = 0; i < 8; i++) tot += red[i];
        float lse    = m + __logf(tot);
        float logit0 = a * qrow[0];
        if (g_counts[k] > 0)
            atomicAdd(out_loss, (lse - logit0) * (1.0f / (float)CH));
    }
}

// ---------------------------------------------------------------------------
extern "C" void kernel_launch(void* const* d_in, const int* in_sizes, int n_in,
                              void* d_out, int out_size) {
    // identify inputs by element count (robust to ordering)
    const float *fea = nullptr, *res = nullptr, *queues = nullptr;
    for (int i = 0; i < n_in; i++) {
        if (in_sizes[i] == BSZ * CH * HW)        fea    = (const float*)d_in[i];
        else if (in_sizes[i] == BSZ * NCLS * HW) res    = (const float*)d_in[i];
        else if (in_sizes[i] == NCLS * CH * NQ)  queues = (const float*)d_in[i];
    }
    float* out      = (float*)d_out;
    float* out_loss = out + (long)BSZ * NCLS * HW;

    init_kernel<<<NCLS, 256>>>(out_loss);
    pred_kernel<<<NPIX / 256, 256>>>(res, out);
    sums_kernel<<<dim3(CH / CPT, BSZ), 256>>>(fea);
    keys_kernel<<<NCLS, 256>>>();
    qsum_kernel<<<(CH * NQ + 255) / 256, 256>>>(queues);
    lse_kernel<<<NCLS * CH, 256>>>(queues, out_loss);
}

// round 2
// speedup vs baseline: 1.2146x; 1.2146x over previous
#include <cuda_runtime.h>

#define NCLS 19
#define CH   256
#define HW   16384      // 128*128
#define BSZ  8
#define NPIX (BSZ*HW)   // 131072
#define NQ   2975
#define INV_T 5.0f      // 1/0.2
#define CPT  4          // channels per thread-block group in sums kernel

// ---- device scratch ----
__device__ float          g_sums[NCLS*CH];
__device__ int            g_counts[NCLS];
__device__ float          g_keys[NCLS*CH];
__device__ unsigned char  g_pred[NPIX];

// pack two floats into a .b64 register pair (lo = a, hi = b)
#define PACKF2(D, A, B) \
    asm("mov.b64 %0, {%1, %2};" : "=l"(D) : "r"(__float_as_uint(A)), "r"(__float_as_uint(B)))

// predicated packed-f32x2 accumulate: if (pk==k) { a01 += v01; a23 += v23; }
#define MASKED_ADD2(A01, A23, PK, K, V01, V23)                              \
    asm volatile("{\n\t.reg .pred p;\n\t"                                   \
                 "setp.eq.s32 p, %2, %3;\n\t"                               \
                 "@p add.rn.f32x2 %0, %0, %4;\n\t"                          \
                 "@p add.rn.f32x2 %1, %1, %5;\n\t}"                         \
                 : "+l"(A01), "+l"(A23)                                     \
                 : "r"(PK), "r"(K), "l"(V01), "l"(V23))

__device__ __forceinline__ float u64_lo_f(unsigned long long x) {
    return __uint_as_float((unsigned)(x & 0xffffffffull));
}
__device__ __forceinline__ float u64_hi_f(unsigned long long x) {
    return __uint_as_float((unsigned)(x >> 32));
}

// ---------------------------------------------------------------------------
// init: zero sums/counts and the loss slot
// ---------------------------------------------------------------------------
__global__ void init_kernel(float* out_loss) {
    int t = blockIdx.x * blockDim.x + threadIdx.x;
    if (t < NCLS * CH) g_sums[t] = 0.0f;
    if (t < NCLS)      g_counts[t] = 0;
    if (t == 0)        *out_loss = 0.0f;
}

// ---------------------------------------------------------------------------
// pred: argmax over classes + copy res -> out + class histogram
// ---------------------------------------------------------------------------
__global__ void pred_kernel(const float* __restrict__ res, float* __restrict__ out) {
    __shared__ int hist[NCLS];
    int tid = threadIdx.x;
    if (tid < NCLS) hist[tid] = 0;
    __syncthreads();

    int t = blockIdx.x * 256 + tid;
    int b = t >> 14;
    int p = t & (HW - 1);
    const float* r = res + b * NCLS * HW + p;
    float*       o = out + b * NCLS * HW + p;

    float best = r[0];
    o[0] = best;
    int bk = 0;
    #pragma unroll
    for (int k = 1; k < NCLS; k++) {
        float v = r[k * HW];
        o[k * HW] = v;
        if (v > best) { best = v; bk = k; }
    }
    g_pred[t] = (unsigned char)bk;
    atomicAdd(&hist[bk], 1);
    __syncthreads();
    if (tid < NCLS) atomicAdd(&g_counts[tid], hist[tid]);
}

// ---------------------------------------------------------------------------
// sums: per-class masked sum of fea via predicated packed f32x2 adds.
// Block = (4-channel group, batch). Each thread: pixel quads (LDG.128 fea,
// uchar4 pred), 19 classes x 4 pixels x 2 packed adds per quad.
// ---------------------------------------------------------------------------
__global__ void __launch_bounds__(256, 2) sums_kernel(const float* __restrict__ fea) {
    int b  = blockIdx.y;
    int c0 = blockIdx.x * CPT;

    unsigned long long a01[NCLS], a23[NCLS];
    #pragma unroll
    for (int k = 0; k < NCLS; k++) { a01[k] = 0ull; a23[k] = 0ull; }

    const float4* f0 = (const float4*)(fea + (size_t)(b * CH + c0 + 0) * HW);
    const float4* f1 = (const float4*)(fea + (size_t)(b * CH + c0 + 1) * HW);
    const float4* f2 = (const float4*)(fea + (size_t)(b * CH + c0 + 2) * HW);
    const float4* f3 = (const float4*)(fea + (size_t)(b * CH + c0 + 3) * HW);
    const uchar4* pr = (const uchar4*)(g_pred + b * HW);

    for (int p4 = threadIdx.x; p4 < HW / 4; p4 += 256) {
        uchar4 pq = pr[p4];
        float4 v0 = f0[p4], v1 = f1[p4], v2 = f2[p4], v3 = f3[p4];
        int pk0 = pq.x, pk1 = pq.y, pk2 = pq.z, pk3 = pq.w;

        unsigned long long x0a, x0b, x1a, x1b, x2a, x2b, x3a, x3b;
        PACKF2(x0a, v0.x, v1.x); PACKF2(x0b, v2.x, v3.x);
        PACKF2(x1a, v0.y, v1.y); PACKF2(x1b, v2.y, v3.y);
        PACKF2(x2a, v0.z, v1.z); PACKF2(x2b, v2.z, v3.z);
        PACKF2(x3a, v0.w, v1.w); PACKF2(x3b, v2.w, v3.w);

        #pragma unroll
        for (int k = 0; k < NCLS; k++) {
            MASKED_ADD2(a01[k], a23[k], pk0, k, x0a, x0b);
            MASKED_ADD2(a01[k], a23[k], pk1, k, x1a, x1b);
            MASKED_ADD2(a01[k], a23[k], pk2, k, x2a, x2b);
            MASKED_ADD2(a01[k], a23[k], pk3, k, x3a, x3b);
        }
    }

    // reduce: warp shfl -> smem across warps -> one atomicAdd per (k, ci)
    __shared__ float wsum[8][NCLS * CPT];   // 8 warps x 76 floats
    int lane = threadIdx.x & 31;
    int wid  = threadIdx.x >> 5;

    #pragma unroll
    for (int k = 0; k < NCLS; k++) {
        float s0 = u64_lo_f(a01[k]);
        float s1 = u64_hi_f(a01[k]);
        float s2 = u64_lo_f(a23[k]);
        float s3 = u64_hi_f(a23[k]);
        #pragma unroll
        for (int o = 16; o; o >>= 1) {
            s0 += __shfl_down_sync(0xffffffffu, s0, o);
            s1 += __shfl_down_sync(0xffffffffu, s1, o);
            s2 += __shfl_down_sync(0xffffffffu, s2, o);
            s3 += __shfl_down_sync(0xffffffffu, s3, o);
        }
        if (lane == 0) {
            wsum[wid][k * CPT + 0] = s0;
            wsum[wid][k * CPT + 1] = s1;
            wsum[wid][k * CPT + 2] = s2;
            wsum[wid][k * CPT + 3] = s3;
        }
    }
    __syncthreads();
    if (threadIdx.x < NCLS * CPT) {
        int j = threadIdx.x;
        float s = 0.0f;
        #pragma unroll
        for (int w = 0; w < 8; w++) s += wsum[w][j];
        int k = j / CPT, i = j % CPT;
        atomicAdd(&g_sums[k * CH + c0 + i], s);
    }
}

// ---------------------------------------------------------------------------
// keys: masked mean + L2 normalize along C. One block per class.
// ---------------------------------------------------------------------------
__global__ void keys_kernel() {
    int k = blockIdx.x;
    int c = threadIdx.x;
    float cnt = (float)max(g_counts[k], 1);
    float v = g_sums[k * CH + c] / cnt;

    __shared__ float red[8];
    __shared__ float snorm;
    float ss = v * v;
    #pragma unroll
    for (int o = 16; o; o >>= 1) ss += __shfl_xor_sync(0xffffffffu, ss, o);
    if ((c & 31) == 0) red[c >> 5] = ss;
    __syncthreads();
    if (c == 0) {
        float t = 0.0f;
        #pragma unroll
        for (int i = 0; i < 8; i++) t += red[i];
        snorm = fmaxf(sqrtf(t), 1e-12f);
    }
    __syncthreads();
    g_keys[k * CH + c] = v / snorm;
}

// ---------------------------------------------------------------------------
// fused qsum + lse: one block per channel c (256 blocks).
// Phase A: accumulate qsum row (over 19 classes) into smem.
// Phase B: per class k, stable LSE over [a*q, a*(qsum-q)] (rows hit L2).
// ---------------------------------------------------------------------------
__global__ void __launch_bounds__(256) lse_kernel(const float* __restrict__ queues,
                                                  float* __restrict__ out_loss) {
    __shared__ float qs[NQ];          // 11.9 KB qsum row for this c
    __shared__ float red[8];
    __shared__ float sval;

    int c   = blockIdx.x;
    int tid = threadIdx.x;

    // Phase A: qsum[c][j] = sum_k queues[k][c][j], register-accumulated
    {
        float s[12];
        #pragma unroll
        for (int i = 0; i < 12; i++) s[i] = 0.0f;
        for (int k = 0; k < NCLS; k++) {
            const float* row = queues + ((size_t)(k * CH + c)) * NQ;
            #pragma unroll
            for (int i = 0; i < 12; i++) {
                int j = tid + i * 256;
                if (j < NQ) s[i] += row[j];
            }
        }
        #pragma unroll
        for (int i = 0; i < 12; i++) {
            int j = tid + i * 256;
            if (j < NQ) qs[j] = s[i];
        }
    }
    __syncthreads();

    float loss_acc = 0.0f;   // only meaningful on tid 0

    for (int k = 0; k < NCLS; k++) {
        float a = g_keys[k * CH + c] * INV_T;
        const float* row = queues + ((size_t)(k * CH + c)) * NQ;

        float q[12];
        float mx = -3.4e38f;
        #pragma unroll
        for (int i = 0; i < 12; i++) {
            int j = tid + i * 256;
            if (j < NQ) {
                q[i] = row[j];
                float x1 = a * q[i];
                float x2 = a * (qs[j] - q[i]);
                mx = fmaxf(mx, fmaxf(x1, x2));
            }
        }

        // block-reduce max
        __syncthreads();                      // protect red[] from previous k
        #pragma unroll
        for (int o = 16; o; o >>= 1) mx = fmaxf(mx, __shfl_xor_sync(0xffffffffu, mx, o));
        if ((tid & 31) == 0) red[tid >> 5] = mx;
        __syncthreads();
        float m = fmaxf(fmaxf(fmaxf(red[0], red[1]), fmaxf(red[2], red[3])),
                        fmaxf(fmaxf(red[4], red[5]), fmaxf(red[6], red[7])));

        float s = 0.0f;
        #pragma unroll
        for (int i = 0; i < 12; i++) {
            int j = tid + i * 256;
            if (j < NQ) {
                float x1 = a * q[i];
                float x2 = a * (qs[j] - q[i]);
                s += __expf(x1 - m) + __expf(x2 - m);
            }
        }

        // block-reduce sum
        __syncthreads();
        #pragma unroll
        for (int o = 16; o; o >>= 1) s += __shfl_xor_sync(0xffffffffu, s, o);
        if ((tid & 31) == 0) red[tid >> 5] = s;
        __syncthreads();
        if (tid == 0) {
            float tot = red[0] + red[1] + red[2] + red[3] +
                        red[4] + red[5] + red[6] + red[7];
            float lse    = m + __logf(tot);
            float logit0 = a * row[0];
            if (g_counts[k] > 0) loss_acc += (lse - logit0) * (1.0f / (float)CH);
        }
    }

    if (tid == 0) atomicAdd(out_loss, loss_acc);
}

// ---------------------------------------------------------------------------
extern "C" void kernel_launch(void* const* d_in, const int* in_sizes, int n_in,
                              void* d_out, int out_size) {
    const float *fea = nullptr, *res = nullptr, *queues = nullptr;
    for (int i = 0; i < n_in; i++) {
        if (in_sizes[i] == BSZ * CH * HW)        fea    = (const float*)d_in[i];
        else if (in_sizes[i] == BSZ * NCLS * HW) res    = (const float*)d_in[i];
        else if (in_sizes[i] == NCLS * CH * NQ)  queues = (const float*)d_in[i];
    }
    float* out      = (float*)d_out;
    float* out_loss = out + (size_t)BSZ * NCLS * HW;

    init_kernel<<<NCLS, 256>>>(out_loss);
    pred_kernel<<<NPIX / 256, 256>>>(res, out);
    sums_kernel<<<dim3(CH / CPT, BSZ), 256>>>(fea);
    keys_kernel<<<NCLS, 256>>>();
    lse_kernel<<<CH, 256>>>(queues, out_loss);
}

// round 4
// speedup vs baseline: 1.4620x; 1.2037x over previous
#include <cuda_runtime.h>

#define NCLS 19
#define CH   256
#define HW   16384      // 128*128
#define BSZ  8
#define NPIX (BSZ*HW)   // 131072
#define NQ   2975
#define INV_T 5.0f      // 1/0.2
#define CPT  2          // channels per block in sums kernel (keeps regs < 128)

// ---- device scratch ----
__device__ float          g_sums[NCLS*CH];
__device__ int            g_counts[NCLS];
__device__ float          g_keys[NCLS*CH];
__device__ unsigned char  g_pred[NPIX];

// pack two floats into a .b64 register pair (lo = a, hi = b)
#define PACKF2(D, A, B) \
    asm("mov.b64 %0, {%1, %2};" : "=l"(D) : "r"(__float_as_uint(A)), "r"(__float_as_uint(B)))

// predicated packed-f32x2 accumulate: if (pk==k) acc += v  (v = {ch0, ch1})
#define MASKED_ADD1(ACC, PK, K, V)                                          \
    asm volatile("{\n\t.reg .pred p;\n\t"                                   \
                 "setp.eq.s32 p, %1, %2;\n\t"                               \
                 "@p add.rn.f32x2 %0, %0, %3;\n\t}"                         \
                 : "+l"(ACC)                                                \
                 : "r"(PK), "r"(K), "l"(V))

__device__ __forceinline__ float u64_lo_f(unsigned long long x) {
    return __uint_as_float((unsigned)(x & 0xffffffffull));
}
__device__ __forceinline__ float u64_hi_f(unsigned long long x) {
    return __uint_as_float((unsigned)(x >> 32));
}

// ---------------------------------------------------------------------------
// init: zero sums/counts and the loss slot
// ---------------------------------------------------------------------------
__global__ void init_kernel(float* out_loss) {
    int t = blockIdx.x * blockDim.x + threadIdx.x;
    if (t < NCLS * CH) g_sums[t] = 0.0f;
    if (t < NCLS)      g_counts[t] = 0;
    if (t == 0)        *out_loss = 0.0f;
}

// ---------------------------------------------------------------------------
// pred: argmax over classes + copy res -> out + class histogram
// ---------------------------------------------------------------------------
__global__ void pred_kernel(const float* __restrict__ res, float* __restrict__ out) {
    __shared__ int hist[NCLS];
    int tid = threadIdx.x;
    if (tid < NCLS) hist[tid] = 0;
    __syncthreads();

    int t = blockIdx.x * 256 + tid;
    int b = t >> 14;
    int p = t & (HW - 1);
    const float* r = res + b * NCLS * HW + p;
    float*       o = out + b * NCLS * HW + p;

    float best = r[0];
    o[0] = best;
    int bk = 0;
    #pragma unroll
    for (int k = 1; k < NCLS; k++) {
        float v = r[k * HW];
        o[k * HW] = v;
        if (v > best) { best = v; bk = k; }
    }
    g_pred[t] = (unsigned char)bk;
    atomicAdd(&hist[bk], 1);
    __syncthreads();
    if (tid < NCLS) atomicAdd(&g_counts[tid], hist[tid]);
}

// ---------------------------------------------------------------------------
// sums: per-class masked sum of fea via predicated packed f32x2 adds.
// Block = (2-channel group, batch). 19 u64 accumulators/thread — no spill.
// ---------------------------------------------------------------------------
__global__ void __launch_bounds__(256, 2) sums_kernel(const float* __restrict__ fea) {
    int b  = blockIdx.y;
    int c0 = blockIdx.x * CPT;

    unsigned long long acc[NCLS];
    #pragma unroll
    for (int k = 0; k < NCLS; k++) acc[k] = 0ull;

    const float4* f0 = (const float4*)(fea + (size_t)(b * CH + c0 + 0) * HW);
    const float4* f1 = (const float4*)(fea + (size_t)(b * CH + c0 + 1) * HW);
    const uchar4* pr = (const uchar4*)(g_pred + b * HW);

    #pragma unroll 2
    for (int p4 = threadIdx.x; p4 < HW / 4; p4 += 256) {
        uchar4 pq = pr[p4];
        float4 v0 = f0[p4], v1 = f1[p4];
        int pk0 = pq.x, pk1 = pq.y, pk2 = pq.z, pk3 = pq.w;

        unsigned long long x0, x1, x2, x3;     // {ch0, ch1} per pixel
        PACKF2(x0, v0.x, v1.x);
        PACKF2(x1, v0.y, v1.y);
        PACKF2(x2, v0.z, v1.z);
        PACKF2(x3, v0.w, v1.w);

        #pragma unroll
        for (int k = 0; k < NCLS; k++) {
            MASKED_ADD1(acc[k], pk0, k, x0);
            MASKED_ADD1(acc[k], pk1, k, x1);
            MASKED_ADD1(acc[k], pk2, k, x2);
            MASKED_ADD1(acc[k], pk3, k, x3);
        }
    }

    // reduce: warp shfl -> smem across warps -> one atomicAdd per (k, ci)
    __shared__ float wsum[8][NCLS * CPT];   // 8 warps x 38 floats
    int lane = threadIdx.x & 31;
    int wid  = threadIdx.x >> 5;

    #pragma unroll
    for (int k = 0; k < NCLS; k++) {
        float s0 = u64_lo_f(acc[k]);
        float s1 = u64_hi_f(acc[k]);
        #pragma unroll
        for (int o = 16; o; o >>= 1) {
            s0 += __shfl_down_sync(0xffffffffu, s0, o);
            s1 += __shfl_down_sync(0xffffffffu, s1, o);
        }
        if (lane == 0) {
            wsum[wid][k * CPT + 0] = s0;
            wsum[wid][k * CPT + 1] = s1;
        }
    }
    __syncthreads();
    if (threadIdx.x < NCLS * CPT) {
        int j = threadIdx.x;
        float s = 0.0f;
        #pragma unroll
        for (int w = 0; w < 8; w++) s += wsum[w][j];
        int k = j / CPT, i = j % CPT;
        atomicAdd(&g_sums[k * CH + c0 + i], s);
    }
}

// ---------------------------------------------------------------------------
// keys: masked mean + L2 normalize along C. One block per class.
// ---------------------------------------------------------------------------
__global__ void keys_kernel() {
    int k = blockIdx.x;
    int c = threadIdx.x;
    float cnt = (float)max(g_counts[k], 1);
    float v = g_sums[k * CH + c] / cnt;

    __shared__ float red[8];
    __shared__ float snorm;
    float ss = v * v;
    #pragma unroll
    for (int o = 16; o; o >>= 1) ss += __shfl_xor_sync(0xffffffffu, ss, o);
    if ((c & 31) == 0) red[c >> 5] = ss;
    __syncthreads();
    if (c == 0) {
        float t = 0.0f;
        #pragma unroll
        for (int i = 0; i < 8; i++) t += red[i];
        snorm = fmaxf(sqrtf(t), 1e-12f);
    }
    __syncthreads();
    g_keys[k * CH + c] = v / snorm;
}

// ---------------------------------------------------------------------------
// fused qsum + lse: grid (CH, 2). Each block: phase A builds the qsum row
// for channel c in smem, phase B handles half the classes' LSE rows.
// ---------------------------------------------------------------------------
__global__ void __launch_bounds__(256) lse_kernel(const float* __restrict__ queues,
                                                  float* __restrict__ out_loss) {
    __shared__ float qs[NQ];          // 11.9 KB qsum row for this c
    __shared__ float red[8];

    int c   = blockIdx.x;
    int tid = threadIdx.x;
    int k0  = blockIdx.y * 10;                 // split: [0,10) and [10,19)
    int k1  = min(k0 + 10, NCLS);

    // Phase A: qsum[c][j] = sum_k queues[k][c][j]
    {
        float s[12];
        #pragma unroll
        for (int i = 0; i < 12; i++) s[i] = 0.0f;
        for (int k = 0; k < NCLS; k++) {
            const float* row = queues + ((size_t)(k * CH + c)) * NQ;
            #pragma unroll
            for (int i = 0; i < 12; i++) {
                int j = tid + i * 256;
                if (j < NQ) s[i] += row[j];
            }
        }
        #pragma unroll
        for (int i = 0; i < 12; i++) {
            int j = tid + i * 256;
            if (j < NQ) qs[j] = s[i];
        }
    }
    __syncthreads();

    float loss_acc = 0.0f;   // only meaningful on tid 0

    for (int k = k0; k < k1; k++) {
        float a = g_keys[k * CH + c] * INV_T;
        const float* row = queues + ((size_t)(k * CH + c)) * NQ;

        float q[12];
        float mx = -3.4e38f;
        #pragma unroll
        for (int i = 0; i < 12; i++) {
            int j = tid + i * 256;
            if (j < NQ) {
                q[i] = row[j];
                float x1 = a * q[i];
                float x2 = a * (qs[j] - q[i]);
                mx = fmaxf(mx, fmaxf(x1, x2));
            }
        }

        __syncthreads();                      // protect red[] from previous k
        #pragma unroll
        for (int o = 16; o; o >>= 1) mx = fmaxf(mx, __shfl_xor_sync(0xffffffffu, mx, o));
        if ((tid & 31) == 0) red[tid >> 5] = mx;
        __syncthreads();
        float m = fmaxf(fmaxf(fmaxf(red[0], red[1]), fmaxf(red[2], red[3])),
                        fmaxf(fmaxf(red[4], red[5]), fmaxf(red[6], red[7])));

        float s = 0.0f;
        #pragma unroll
        for (int i = 0; i < 12; i++) {
            int j = tid + i * 256;
            if (j < NQ) {
                float x1 = a * q[i];
                float x2 = a * (qs[j] - q[i]);
                s += __expf(x1 - m) + __expf(x2 - m);
            }
        }

        __syncthreads();
        #pragma unroll
        for (int o = 16; o; o >>= 1) s += __shfl_xor_sync(0xffffffffu, s, o);
        if ((tid & 31) == 0) red[tid >> 5] = s;
        __syncthreads();
        if (tid == 0) {
            float tot = red[0] + red[1] + red[2] + red[3] +
                        red[4] + red[5] + red[6] + red[7];
            float lse    = m + __logf(tot);
            float logit0 = a * row[0];
            if (g_counts[k] > 0) loss_acc += (lse - logit0) * (1.0f / (float)CH);
        }
    }

    if (tid == 0) atomicAdd(out_loss, loss_acc);
}

// ---------------------------------------------------------------------------
extern "C" void kernel_launch(void* const* d_in, const int* in_sizes, int n_in,
                              void* d_out, int out_size) {
    const float *fea = nullptr, *res = nullptr, *queues = nullptr;
    for (int i = 0; i < n_in; i++) {
        if (in_sizes[i] == BSZ * CH * HW)        fea    = (const float*)d_in[i];
        else if (in_sizes[i] == BSZ * NCLS * HW) res    = (const float*)d_in[i];
        else if (in_sizes[i] == NCLS * CH * NQ)  queues = (const float*)d_in[i];
    }
    float* out      = (float*)d_out;
    float* out_loss = out + (size_t)BSZ * NCLS * HW;

    init_kernel<<<NCLS, 256>>>(out_loss);
    pred_kernel<<<NPIX / 256, 256>>>(res, out);
    sums_kernel<<<dim3(CH / CPT, BSZ), 256>>>(fea);
    keys_kernel<<<NCLS, 256>>>();
    lse_kernel<<<dim3(CH, 2), 256>>>(queues, out_loss);
}